// round 4
// baseline (speedup 1.0000x reference)
#include <cuda_runtime.h>
#include <math.h>
#include <stdint.h>

#define NN 100000
#define DD 128
#define NE 1600000

#define TILE_M 256
#define MLP_THREADS 512
#define HSTRIDE 132   // 132 % 32 == 4 -> A-frag reads conflict-free (4g + t4 bijective)

// Scratch (allocation-free rule: __device__ globals)
__device__ float g_mi[(size_t)NN * DD];
__device__ float g_mo[(size_t)NN * DD];

__device__ int  g_cnt_in[NN];
__device__ int  g_cnt_out[NN];
__device__ int  g_off_in[NN + 1];
__device__ int  g_off_out[NN + 1];
__device__ int  g_cur_in[NN];
__device__ int  g_cur_out[NN];
__device__ int2 g_lst_in[NE];    // {src, weight-bits}, keyed by dst
__device__ int2 g_lst_out[NE];   // {dst, weight-bits}, keyed by src

// ---------------------------------------------------------------------------
__global__ void hist_kernel(const int* __restrict__ ei,
                            int* __restrict__ cin, int* __restrict__ cout) {
    int i = blockIdx.x * blockDim.x + threadIdx.x;
    if (i >= NE) return;
    int s = ei[i];
    int t = ei[NE + i];
    atomicAdd(&cin[t], 1);
    atomicAdd(&cout[s], 1);
}

// ---------------------------------------------------------------------------
#define SCAN_CHUNK 98
__global__ __launch_bounds__(1024) void scan_kernel(
    const int* __restrict__ cin, int* __restrict__ offin, int* __restrict__ curin,
    const int* __restrict__ cout, int* __restrict__ offout, int* __restrict__ curout) {
    const int* cnt = blockIdx.x == 0 ? cin : cout;
    int* off = blockIdx.x == 0 ? offin : offout;
    int* cur = blockIdx.x == 0 ? curin : curout;

    __shared__ int ssum[1024];
    int t = threadIdx.x;
    int base = t * SCAN_CHUNK;

    int s = 0;
#pragma unroll 4
    for (int k = 0; k < SCAN_CHUNK; k++) {
        int idx = base + k;
        if (idx < NN) s += cnt[idx];
    }
    ssum[t] = s;
    __syncthreads();

    for (int o = 1; o < 1024; o <<= 1) {
        int v = (t >= o) ? ssum[t - o] : 0;
        __syncthreads();
        ssum[t] += v;
        __syncthreads();
    }

    int run = (t > 0) ? ssum[t - 1] : 0;
#pragma unroll 4
    for (int k = 0; k < SCAN_CHUNK; k++) {
        int idx = base + k;
        if (idx < NN) {
            int c = cnt[idx];
            off[idx] = run;
            cur[idx] = run;
            run += c;
        }
    }
    if (t == 0) off[NN] = ssum[1023];
}

// ---------------------------------------------------------------------------
__global__ void fill_kernel(const int* __restrict__ ei, const float* __restrict__ e,
                            int* __restrict__ curin, int* __restrict__ curout,
                            int2* __restrict__ lin, int2* __restrict__ lout) {
    int i = blockIdx.x * blockDim.x + threadIdx.x;
    if (i >= NE) return;
    int s = ei[i];
    int t = ei[NE + i];
    int wb = __float_as_int(e[i]);
    int p1 = atomicAdd(&curin[t], 1);
    lin[p1] = make_int2(s, wb);
    int p2 = atomicAdd(&curout[s], 1);
    lout[p2] = make_int2(t, wb);
}

// ---------------------------------------------------------------------------
// Merged gather: warps [0, NN) -> mi via lin; warps [NN, 2NN) -> mo via lout.
// ---------------------------------------------------------------------------
__global__ __launch_bounds__(256) void gather_kernel(
    const float* __restrict__ x,
    const int* __restrict__ offin, const int2* __restrict__ lin,
    const int* __restrict__ offout, const int2* __restrict__ lout,
    float* __restrict__ mi, float* __restrict__ mo) {
    int wg = (blockIdx.x * blockDim.x + threadIdx.x) >> 5;
    int lane = threadIdx.x & 31;
    if (wg >= 2 * NN) return;

    const int* off;
    const int2* lst;
    float* dst;
    int node;
    if (wg < NN) { node = wg; off = offin; lst = lin; dst = mi; }
    else         { node = wg - NN; off = offout; lst = lout; dst = mo; }

    int beg = off[node];
    int end = off[node + 1];

    float4 acc = make_float4(0.f, 0.f, 0.f, 0.f);

    int j = beg;
    for (; j + 8 <= end; j += 8) {
        int2 p[8];
#pragma unroll
        for (int u = 0; u < 8; u++) p[u] = __ldg(&lst[j + u]);
        float4 v[8];
#pragma unroll
        for (int u = 0; u < 8; u++)
            v[u] = __ldg((const float4*)(x + (size_t)p[u].x * DD) + lane);
#pragma unroll
        for (int u = 0; u < 8; u++) {
            float w = __int_as_float(p[u].y);
            acc.x = fmaf(w, v[u].x, acc.x); acc.y = fmaf(w, v[u].y, acc.y);
            acc.z = fmaf(w, v[u].z, acc.z); acc.w = fmaf(w, v[u].w, acc.w);
        }
    }
    for (; j < end; j++) {
        int2 p0 = __ldg(&lst[j]);
        float4 v0 = __ldg((const float4*)(x + (size_t)p0.x * DD) + lane);
        float w0 = __int_as_float(p0.y);
        acc.x = fmaf(w0, v0.x, acc.x); acc.y = fmaf(w0, v0.y, acc.y);
        acc.z = fmaf(w0, v0.z, acc.z); acc.w = fmaf(w0, v0.w, acc.w);
    }

    ((float4*)(dst + (size_t)node * DD))[lane] = acc;
}

// ---------------------------------------------------------------------------
// Fully fused 4-layer MLP: GEMM0([mi|mo|x] @ W0) + LN + tanh, then 3x
// (h @ W[l] + LN + tanh), all in one kernel. 256-row tile resident in smem.
// Block: 512 threads = 16 warps; warp w owns rows [w*16, w*16+16).
// ---------------------------------------------------------------------------
__device__ __forceinline__ uint32_t f2tf32(float v) {
    uint32_t r;
    asm("cvt.rna.tf32.f32 %0, %1;" : "=r"(r) : "f"(v));
    return r;
}

__device__ __forceinline__ float fast_tanh(float x) {
    float ax = fabsf(x);
    float t = __expf(-2.f * ax);            // in (0,1]
    float r = (1.f - t) * __frcp_rn(1.f + t);
    return copysignf(r, x);
}

__global__ __launch_bounds__(MLP_THREADS, 1) void mlp_fused(
    const float* __restrict__ A0, const float* __restrict__ A1,
    const float* __restrict__ A2,
    const float* __restrict__ W0,   // [384,128]
    const float* __restrict__ b0v, const float* __restrict__ g0v,
    const float* __restrict__ be0v,
    const float* __restrict__ W,    // [3,128,128]
    const float* __restrict__ bv, const float* __restrict__ gv,
    const float* __restrict__ bev,
    float* __restrict__ out)
{
    extern __shared__ uint32_t smem[];
    uint32_t* H  = smem;                         // [TILE_M][HSTRIDE] tf32
    uint32_t* Ws = smem + TILE_M * HSTRIDE;      // [32][132]
    uint32_t* As0 = H;                           // layer-0 staging [TILE_M][36] (aliases H)

    const int tid = threadIdx.x;
    const int lane = tid & 31;
    const int wid = tid >> 5;
    const int g = lane >> 2;
    const int t4 = lane & 3;
    const int row0 = blockIdx.x * TILE_M;
    const int wrow = wid * 16;

    float c[16][4];
#pragma unroll
    for (int j = 0; j < 16; j++)
#pragma unroll
        for (int q = 0; q < 4; q++) c[j][q] = 0.f;

    // ---------------- Layer 0: K = 384 over {mi, mo, x} ----------------
    const float* Ap[3] = {A0, A1, A2};
    for (int m = 0; m < 3; m++) {
        const float4* A4 = (const float4*)(Ap[m]);
        const float4* W4 = (const float4*)W0;
        for (int kc = 0; kc < 4; kc++) {
            __syncthreads();
            // A chunk: 256 rows x 32 k = 2048 float4, 4 per thread
#pragma unroll
            for (int i = 0; i < 4; i++) {
                int idx = tid + i * MLP_THREADS;
                int r = idx >> 3;
                int c4 = idx & 7;
                int grow = row0 + r;
                if (grow >= NN) grow = 0;
                float4 v = __ldg(&A4[(size_t)grow * 32 + kc * 8 + c4]);
                uint32_t* p = As0 + r * 36 + c4 * 4;
                p[0] = f2tf32(v.x); p[1] = f2tf32(v.y);
                p[2] = f2tf32(v.z); p[3] = f2tf32(v.w);
            }
            // W chunk: rows [m*128+kc*32, +32) x 128 cols = 1024 float4, 2/thread
#pragma unroll
            for (int i = 0; i < 2; i++) {
                int idx = tid + i * MLP_THREADS;
                int k = idx >> 5;
                int n4 = idx & 31;
                float4 v = __ldg(&W4[(size_t)(m * 128 + kc * 32 + k) * 32 + n4]);
                uint32_t* p = Ws + k * 132 + n4 * 4;
                p[0] = f2tf32(v.x); p[1] = f2tf32(v.y);
                p[2] = f2tf32(v.z); p[3] = f2tf32(v.w);
            }
            __syncthreads();

#pragma unroll
            for (int ks = 0; ks < 4; ks++) {
                uint32_t a0 = As0[(wrow + g) * 36 + ks * 8 + t4];
                uint32_t a1 = As0[(wrow + g + 8) * 36 + ks * 8 + t4];
                uint32_t a2 = As0[(wrow + g) * 36 + ks * 8 + t4 + 4];
                uint32_t a3 = As0[(wrow + g + 8) * 36 + ks * 8 + t4 + 4];
#pragma unroll
                for (int j = 0; j < 16; j++) {
                    uint32_t bb0 = Ws[(ks * 8 + t4) * 132 + j * 8 + g];
                    uint32_t bb1 = Ws[(ks * 8 + t4 + 4) * 132 + j * 8 + g];
                    asm volatile(
                        "mma.sync.aligned.m16n8k8.row.col.f32.tf32.tf32.f32 "
                        "{%0,%1,%2,%3}, {%4,%5,%6,%7}, {%8,%9}, {%0,%1,%2,%3};"
                        : "+f"(c[j][0]), "+f"(c[j][1]), "+f"(c[j][2]), "+f"(c[j][3])
                        : "r"(a0), "r"(a1), "r"(a2), "r"(a3), "r"(bb0), "r"(bb1));
                }
            }
        }
    }
    // All warps must be done reading As0 (aliases H) before epilogue writes H.
    __syncthreads();

    const int grow1 = row0 + wrow + g;
    const int grow2 = grow1 + 8;

    // ---------------- 4 epilogues + 3 inner layers ----------------
    for (int l = 0; l < 4; l++) {
        const float* bias  = (l == 0) ? b0v  : bv  + (l - 1) * 128;
        const float* gamma = (l == 0) ? g0v  : gv  + (l - 1) * 128;
        const float* beta  = (l == 0) ? be0v : bev + (l - 1) * 128;

        // Epilogue: bias + LN + tanh on c[][]
        float s1 = 0.f, q1 = 0.f, s2 = 0.f, q2 = 0.f;
#pragma unroll
        for (int j = 0; j < 16; j++) {
            int col = j * 8 + 2 * t4;
            float2 bb = __ldg((const float2*)(bias + col));
            c[j][0] += bb.x; c[j][1] += bb.y;
            c[j][2] += bb.x; c[j][3] += bb.y;
            s1 += c[j][0] + c[j][1];
            q1 += c[j][0] * c[j][0] + c[j][1] * c[j][1];
            s2 += c[j][2] + c[j][3];
            q2 += c[j][2] * c[j][2] + c[j][3] * c[j][3];
        }
#pragma unroll
        for (int o = 1; o <= 2; o <<= 1) {
            s1 += __shfl_xor_sync(0xFFFFFFFFu, s1, o);
            q1 += __shfl_xor_sync(0xFFFFFFFFu, q1, o);
            s2 += __shfl_xor_sync(0xFFFFFFFFu, s2, o);
            q2 += __shfl_xor_sync(0xFFFFFFFFu, q2, o);
        }
        float m1 = s1 * (1.f / 128.f);
        float r1 = rsqrtf(q1 * (1.f / 128.f) - m1 * m1 + 1e-5f);
        float m2 = s2 * (1.f / 128.f);
        float r2 = rsqrtf(q2 * (1.f / 128.f) - m2 * m2 + 1e-5f);

        if (l == 3) {
            // Final: write fp32 to out
#pragma unroll
            for (int j = 0; j < 16; j++) {
                int col = j * 8 + 2 * t4;
                float2 gg = __ldg((const float2*)(gamma + col));
                float2 ee = __ldg((const float2*)(beta + col));
                if (grow1 < NN) {
                    float2 o1;
                    o1.x = fast_tanh((c[j][0] - m1) * r1 * gg.x + ee.x);
                    o1.y = fast_tanh((c[j][1] - m1) * r1 * gg.y + ee.y);
                    *(float2*)(out + (size_t)grow1 * DD + col) = o1;
                }
                if (grow2 < NN) {
                    float2 o2;
                    o2.x = fast_tanh((c[j][2] - m2) * r2 * gg.x + ee.x);
                    o2.y = fast_tanh((c[j][3] - m2) * r2 * gg.y + ee.y);
                    *(float2*)(out + (size_t)grow2 * DD + col) = o2;
                }
            }
            break;
        }

        // Intermediate: write tf32 h into H (warp-private rows)
#pragma unroll
        for (int j = 0; j < 16; j++) {
            int col = j * 8 + 2 * t4;
            float2 gg = __ldg((const float2*)(gamma + col));
            float2 ee = __ldg((const float2*)(beta + col));
            float h00 = fast_tanh((c[j][0] - m1) * r1 * gg.x + ee.x);
            float h01 = fast_tanh((c[j][1] - m1) * r1 * gg.y + ee.y);
            float h10 = fast_tanh((c[j][2] - m2) * r2 * gg.x + ee.x);
            float h11 = fast_tanh((c[j][3] - m2) * r2 * gg.y + ee.y);
            uint32_t* p1 = H + (wrow + g) * HSTRIDE + col;
            uint32_t* p2 = H + (wrow + g + 8) * HSTRIDE + col;
            p1[0] = f2tf32(h00); p1[1] = f2tf32(h01);
            p2[0] = f2tf32(h10); p2[1] = f2tf32(h11);
            // reset accumulators for next layer
            c[j][0] = 0.f; c[j][1] = 0.f; c[j][2] = 0.f; c[j][3] = 0.f;
        }

        // Next layer GEMM: h (in H) @ W[l]  (K = 128)
        const float4* W4 = (const float4*)(W + (size_t)l * 128 * 128);
        for (int kc = 0; kc < 4; kc++) {
            __syncthreads();   // all H writes visible / Ws free
#pragma unroll
            for (int i = 0; i < 2; i++) {
                int idx = tid + i * MLP_THREADS;
                int k = idx >> 5;
                int n4 = idx & 31;
                float4 v = __ldg(&W4[(size_t)(kc * 32 + k) * 32 + n4]);
                uint32_t* p = Ws + k * 132 + n4 * 4;
                p[0] = f2tf32(v.x); p[1] = f2tf32(v.y);
                p[2] = f2tf32(v.z); p[3] = f2tf32(v.w);
            }
            __syncthreads();

#pragma unroll
            for (int ks = 0; ks < 4; ks++) {
                int kidx = kc * 32 + ks * 8 + t4;
                uint32_t a0 = H[(wrow + g) * HSTRIDE + kidx];
                uint32_t a1 = H[(wrow + g + 8) * HSTRIDE + kidx];
                uint32_t a2 = H[(wrow + g) * HSTRIDE + kidx + 4];
                uint32_t a3 = H[(wrow + g + 8) * HSTRIDE + kidx + 4];
#pragma unroll
                for (int j = 0; j < 16; j++) {
                    uint32_t bb0 = Ws[(ks * 8 + t4) * 132 + j * 8 + g];
                    uint32_t bb1 = Ws[(ks * 8 + t4 + 4) * 132 + j * 8 + g];
                    asm volatile(
                        "mma.sync.aligned.m16n8k8.row.col.f32.tf32.tf32.f32 "
                        "{%0,%1,%2,%3}, {%4,%5,%6,%7}, {%8,%9}, {%0,%1,%2,%3};"
                        : "+f"(c[j][0]), "+f"(c[j][1]), "+f"(c[j][2]), "+f"(c[j][3])
                        : "r"(a0), "r"(a1), "r"(a2), "r"(a3), "r"(bb0), "r"(bb1));
                }
            }
        }
        __syncthreads();   // all warps done with this layer's H reads... (own rows only, but Ws reuse needs it anyway on next iteration's first sync)
    }
}

// ---------------------------------------------------------------------------
extern "C" void kernel_launch(void* const* d_in, const int* in_sizes, int n_in,
                              void* d_out, int out_size) {
    const float* x   = (const float*)d_in[0];
    const float* e   = (const float*)d_in[1];
    const int*   ei  = (const int*)d_in[2];
    const float* W0  = (const float*)d_in[3];
    const float* b0  = (const float*)d_in[4];
    const float* g0  = (const float*)d_in[5];
    const float* be0 = (const float*)d_in[6];
    const float* W   = (const float*)d_in[7];
    const float* b   = (const float*)d_in[8];
    const float* g   = (const float*)d_in[9];
    const float* be  = (const float*)d_in[10];
    float* out = (float*)d_out;

    float *mi, *mo;
    int *cin, *cout_, *offin, *offout, *curin, *curout;
    int2 *lin, *lout;
    cudaGetSymbolAddress((void**)&mi, g_mi);
    cudaGetSymbolAddress((void**)&mo, g_mo);
    cudaGetSymbolAddress((void**)&cin, g_cnt_in);
    cudaGetSymbolAddress((void**)&cout_, g_cnt_out);
    cudaGetSymbolAddress((void**)&offin, g_off_in);
    cudaGetSymbolAddress((void**)&offout, g_off_out);
    cudaGetSymbolAddress((void**)&curin, g_cur_in);
    cudaGetSymbolAddress((void**)&curout, g_cur_out);
    cudaGetSymbolAddress((void**)&lin, g_lst_in);
    cudaGetSymbolAddress((void**)&lout, g_lst_out);

    static int smem_set = 0;
    const int smem_bytes = (TILE_M * HSTRIDE + 32 * 132) * 4;  // ~152 KB
    if (!smem_set) {
        cudaFuncSetAttribute(mlp_fused,
                             cudaFuncAttributeMaxDynamicSharedMemorySize,
                             smem_bytes);
        smem_set = 1;
    }

    cudaMemsetAsync(cin, 0, NN * sizeof(int));
    cudaMemsetAsync(cout_, 0, NN * sizeof(int));

    hist_kernel<<<(NE + 255) / 256, 256>>>(ei, cin, cout_);
    scan_kernel<<<2, 1024>>>(cin, offin, curin, cout_, offout, curout);
    fill_kernel<<<(NE + 255) / 256, 256>>>(ei, e, curin, curout, lin, lout);

    {
        long long warps = 2LL * NN;
        int blocks = (int)((warps * 32 + 255) / 256);
        gather_kernel<<<blocks, 256>>>(x, offin, lin, offout, lout, mi, mo);
    }

    const int gblocks = (NN + TILE_M - 1) / TILE_M;  // 391
    mlp_fused<<<gblocks, MLP_THREADS, smem_bytes>>>(
        mi, mo, x, W0, b0, g0, be0, W, b, g, be, out);
}

// round 5
// speedup vs baseline: 1.1374x; 1.1374x over previous
#include <cuda_runtime.h>
#include <math.h>
#include <stdint.h>

#define NN 100000
#define DD 128
#define NE 1600000

#define TILE_M 128
#define MLP_THREADS 256
#define HSTRIDE 132       // H row stride (words); (g*132+t4)%32 bijective -> conflict-free
#define WBSTRIDE 36       // per-lane B-frag region stride (words), 144B: LDS.128-friendly

// Scratch (allocation-free rule: __device__ globals)
__device__ float g_mi[(size_t)NN * DD];
__device__ float g_mo[(size_t)NN * DD];

__device__ int  g_cnt[2 * NN];          // [0,NN): in-degree, [NN,2NN): out-degree
__device__ int  g_off_in[NN + 1];
__device__ int  g_off_out[NN + 1];
__device__ int  g_cur_in[NN];
__device__ int  g_cur_out[NN];
__device__ int2 g_lst_in[NE];    // {src, weight-bits}, keyed by dst
__device__ int2 g_lst_out[NE];   // {dst, weight-bits}, keyed by src

// ---------------------------------------------------------------------------
// Histogram of edge endpoints (4 edges per thread, vectorized reads)
// ---------------------------------------------------------------------------
__global__ void hist_kernel(const int* __restrict__ ei, int* __restrict__ cnt) {
    int i = blockIdx.x * blockDim.x + threadIdx.x;
    if (i >= NE / 4) return;
    int4 s = __ldg((const int4*)ei + i);
    int4 t = __ldg((const int4*)(ei + NE) + i);
    atomicAdd(&cnt[t.x], 1); atomicAdd(&cnt[t.y], 1);
    atomicAdd(&cnt[t.z], 1); atomicAdd(&cnt[t.w], 1);
    atomicAdd(&cnt[NN + s.x], 1); atomicAdd(&cnt[NN + s.y], 1);
    atomicAdd(&cnt[NN + s.z], 1); atomicAdd(&cnt[NN + s.w], 1);
}

// ---------------------------------------------------------------------------
// Exclusive scan of a 100k counter array. One 1024-thread block per array.
// ---------------------------------------------------------------------------
#define SCAN_CHUNK 98
__global__ __launch_bounds__(1024) void scan_kernel(
    const int* __restrict__ cntbuf,
    int* __restrict__ offin, int* __restrict__ curin,
    int* __restrict__ offout, int* __restrict__ curout) {
    const int* cnt = cntbuf + blockIdx.x * NN;
    int* off = blockIdx.x == 0 ? offin : offout;
    int* cur = blockIdx.x == 0 ? curin : curout;

    __shared__ int ssum[1024];
    int t = threadIdx.x;
    int base = t * SCAN_CHUNK;

    int s = 0;
#pragma unroll 4
    for (int k = 0; k < SCAN_CHUNK; k++) {
        int idx = base + k;
        if (idx < NN) s += cnt[idx];
    }
    ssum[t] = s;
    __syncthreads();

    for (int o = 1; o < 1024; o <<= 1) {
        int v = (t >= o) ? ssum[t - o] : 0;
        __syncthreads();
        ssum[t] += v;
        __syncthreads();
    }

    int run = (t > 0) ? ssum[t - 1] : 0;
#pragma unroll 4
    for (int k = 0; k < SCAN_CHUNK; k++) {
        int idx = base + k;
        if (idx < NN) {
            int c = cnt[idx];
            off[idx] = run;
            cur[idx] = run;
            run += c;
        }
    }
    if (t == 0) off[NN] = ssum[1023];
}

// ---------------------------------------------------------------------------
// Fill CSR edge lists (atomic cursors), 4 edges per thread
// ---------------------------------------------------------------------------
__global__ void fill_kernel(const int* __restrict__ ei, const float* __restrict__ e,
                            int* __restrict__ curin, int* __restrict__ curout,
                            int2* __restrict__ lin, int2* __restrict__ lout) {
    int i = blockIdx.x * blockDim.x + threadIdx.x;
    if (i >= NE / 4) return;
    int4 s = __ldg((const int4*)ei + i);
    int4 t = __ldg((const int4*)(ei + NE) + i);
    float4 w = __ldg((const float4*)e + i);
    int ss[4] = {s.x, s.y, s.z, s.w};
    int tt[4] = {t.x, t.y, t.z, t.w};
    float ww[4] = {w.x, w.y, w.z, w.w};
#pragma unroll
    for (int u = 0; u < 4; u++) {
        int wb = __float_as_int(ww[u]);
        int p1 = atomicAdd(&curin[tt[u]], 1);
        lin[p1] = make_int2(ss[u], wb);
        int p2 = atomicAdd(&curout[ss[u]], 1);
        lout[p2] = make_int2(tt[u], wb);
    }
}

// ---------------------------------------------------------------------------
// Merged gather: warps [0, NN) -> mi via lin; warps [NN, 2NN) -> mo via lout.
// ---------------------------------------------------------------------------
__global__ __launch_bounds__(256) void gather_kernel(
    const float* __restrict__ x,
    const int* __restrict__ offin, const int2* __restrict__ lin,
    const int* __restrict__ offout, const int2* __restrict__ lout,
    float* __restrict__ mi, float* __restrict__ mo) {
    int wg = (blockIdx.x * blockDim.x + threadIdx.x) >> 5;
    int lane = threadIdx.x & 31;
    if (wg >= 2 * NN) return;

    const int* off;
    const int2* lst;
    float* dst;
    int node;
    if (wg < NN) { node = wg; off = offin; lst = lin; dst = mi; }
    else         { node = wg - NN; off = offout; lst = lout; dst = mo; }

    int beg = off[node];
    int end = off[node + 1];

    float4 acc = make_float4(0.f, 0.f, 0.f, 0.f);

    int j = beg;
    for (; j + 8 <= end; j += 8) {
        int2 p[8];
#pragma unroll
        for (int u = 0; u < 8; u++) p[u] = __ldg(&lst[j + u]);
        float4 v[8];
#pragma unroll
        for (int u = 0; u < 8; u++)
            v[u] = __ldg((const float4*)(x + (size_t)p[u].x * DD) + lane);
#pragma unroll
        for (int u = 0; u < 8; u++) {
            float w = __int_as_float(p[u].y);
            acc.x = fmaf(w, v[u].x, acc.x); acc.y = fmaf(w, v[u].y, acc.y);
            acc.z = fmaf(w, v[u].z, acc.z); acc.w = fmaf(w, v[u].w, acc.w);
        }
    }
    for (; j < end; j++) {
        int2 p0 = __ldg(&lst[j]);
        float4 v0 = __ldg((const float4*)(x + (size_t)p0.x * DD) + lane);
        float w0 = __int_as_float(p0.y);
        acc.x = fmaf(w0, v0.x, acc.x); acc.y = fmaf(w0, v0.y, acc.y);
        acc.z = fmaf(w0, v0.z, acc.z); acc.w = fmaf(w0, v0.w, acc.w);
    }

    ((float4*)(dst + (size_t)node * DD))[lane] = acc;
}

// ---------------------------------------------------------------------------
// Fully fused 4-layer MLP. Tile 128 rows resident in smem, tf32 mma.
// Block: 256 threads = 8 warps, 2 blocks/SM. Warp w owns rows [w*16, w*16+16).
// B (weights) staged in FRAGMENT-MAJOR smem layout: the inner loop reads them
// as 8x LDS.128 per k-step instead of 32x LDS.32.
// ---------------------------------------------------------------------------
__device__ __forceinline__ uint32_t f2tf32(float v) {
    uint32_t r;
    asm("cvt.rna.tf32.f32 %0, %1;" : "=r"(r) : "f"(v));
    return r;
}

__device__ __forceinline__ float fast_tanh(float x) {
    float ax = fabsf(x);
    float t = __expf(-2.f * ax);
    float r = (1.f - t) * __frcp_rn(1.f + t);
    return copysignf(r, x);
}

#define MMA4(cj, A0r, A1r, A2r, A3r, B0r, B1r)                                   \
    asm volatile(                                                                \
        "mma.sync.aligned.m16n8k8.row.col.f32.tf32.tf32.f32 "                    \
        "{%0,%1,%2,%3}, {%4,%5,%6,%7}, {%8,%9}, {%0,%1,%2,%3};"                  \
        : "+f"(cj[0]), "+f"(cj[1]), "+f"(cj[2]), "+f"(cj[3])                     \
        : "r"(A0r), "r"(A1r), "r"(A2r), "r"(A3r), "r"(B0r), "r"(B1r))

__global__ __launch_bounds__(MLP_THREADS, 2) void mlp_fused(
    const float* __restrict__ A0, const float* __restrict__ A1,
    const float* __restrict__ A2,
    const float* __restrict__ W0,   // [384,128]
    const float* __restrict__ b0v, const float* __restrict__ g0v,
    const float* __restrict__ be0v,
    const float* __restrict__ W,    // [3,128,128]
    const float* __restrict__ bv, const float* __restrict__ gv,
    const float* __restrict__ bev,
    float* __restrict__ out)
{
    extern __shared__ uint32_t smem[];
    uint32_t* H  = smem;                        // [TILE_M][HSTRIDE] tf32
    uint32_t* WB = smem + TILE_M * HSTRIDE;     // frag-major: [4 ks][32 lane][WBSTRIDE]
    uint32_t* As0 = H;                          // layer-0 A staging [TILE_M][36] (aliases H)

    const int tid = threadIdx.x;
    const int lane = tid & 31;
    const int wid = tid >> 5;
    const int g = lane >> 2;
    const int t4 = lane & 3;
    const int row0 = blockIdx.x * TILE_M;
    const int wrow = wid * 16;

    float c[16][4];
#pragma unroll
    for (int j = 0; j < 16; j++)
#pragma unroll
        for (int q = 0; q < 4; q++) c[j][q] = 0.f;

    // Frag-major W staging: element (k in [0,32), n in [0,128)) of the chunk
    // lands at WB[(ks*32 + (g*4+t4))*WBSTRIDE + j*2 + slot]
    //   ks=k>>3, r=k&7, slot=r>>2, t4=r&3, j=n>>3, g=n&7.
    // Inner-loop read per lane per ks: 8x LDS.128 covering j=2q,2q+1 pairs.

    // ---------------- Layer 0: K = 384 over {mi, mo, x} ----------------
    const float* Ap[3] = {A0, A1, A2};
    for (int m = 0; m < 3; m++) {
        const float4* A4 = (const float4*)(Ap[m]);
        const float4* W4 = (const float4*)W0;
        for (int kc = 0; kc < 4; kc++) {
            __syncthreads();
            // A chunk: 128 rows x 32 k = 1024 float4, 4 per thread
#pragma unroll
            for (int i = 0; i < 4; i++) {
                int idx = tid + i * MLP_THREADS;
                int r = idx >> 3;
                int c4 = idx & 7;
                int grow = row0 + r;
                if (grow >= NN) grow = 0;
                float4 v = __ldg(&A4[(size_t)grow * 32 + kc * 8 + c4]);
                uint32_t* p = As0 + r * 36 + c4 * 4;
                p[0] = f2tf32(v.x); p[1] = f2tf32(v.y);
                p[2] = f2tf32(v.z); p[3] = f2tf32(v.w);
            }
            // W chunk (frag-major): 32 k x 128 n = 1024 float4, 4 per thread
#pragma unroll
            for (int i = 0; i < 4; i++) {
                int idx = tid + i * MLP_THREADS;
                int k = idx >> 5;
                int n4 = idx & 31;
                float4 v = __ldg(&W4[(size_t)(m * 128 + kc * 32 + k) * 32 + n4]);
                int ks = k >> 3, r = k & 7;
                int slot = r >> 2, t4w = r & 3;
                float vv[4] = {v.x, v.y, v.z, v.w};
#pragma unroll
                for (int cc = 0; cc < 4; cc++) {
                    int n = n4 * 4 + cc;
                    int jj = n >> 3, gg = n & 7;
                    WB[(ks * 32 + gg * 4 + t4w) * WBSTRIDE + jj * 2 + slot] = f2tf32(vv[cc]);
                }
            }
            __syncthreads();

#pragma unroll
            for (int ks = 0; ks < 4; ks++) {
                uint32_t a0 = As0[(wrow + g) * 36 + ks * 8 + t4];
                uint32_t a1 = As0[(wrow + g + 8) * 36 + ks * 8 + t4];
                uint32_t a2 = As0[(wrow + g) * 36 + ks * 8 + t4 + 4];
                uint32_t a3 = As0[(wrow + g + 8) * 36 + ks * 8 + t4 + 4];
                const uint4* wb = (const uint4*)(WB + (ks * 32 + lane) * WBSTRIDE);
#pragma unroll
                for (int q = 0; q < 8; q++) {
                    uint4 bb = wb[q];
                    MMA4(c[2 * q],     a0, a1, a2, a3, bb.x, bb.y);
                    MMA4(c[2 * q + 1], a0, a1, a2, a3, bb.z, bb.w);
                }
            }
        }
    }
    // All warps must be done reading As0 (aliases H) before epilogue writes H.
    __syncthreads();

    const int grow1 = row0 + wrow + g;
    const int grow2 = grow1 + 8;

    // ---------------- 4 epilogues + 3 inner layers ----------------
    for (int l = 0; l < 4; l++) {
        const float* bias  = (l == 0) ? b0v  : bv  + (l - 1) * 128;
        const float* gamma = (l == 0) ? g0v  : gv  + (l - 1) * 128;
        const float* beta  = (l == 0) ? be0v : bev + (l - 1) * 128;

        float s1 = 0.f, q1 = 0.f, s2 = 0.f, q2 = 0.f;
#pragma unroll
        for (int j = 0; j < 16; j++) {
            int col = j * 8 + 2 * t4;
            float2 bb = __ldg((const float2*)(bias + col));
            c[j][0] += bb.x; c[j][1] += bb.y;
            c[j][2] += bb.x; c[j][3] += bb.y;
            s1 += c[j][0] + c[j][1];
            q1 += c[j][0] * c[j][0] + c[j][1] * c[j][1];
            s2 += c[j][2] + c[j][3];
            q2 += c[j][2] * c[j][2] + c[j][3] * c[j][3];
        }
#pragma unroll
        for (int o = 1; o <= 2; o <<= 1) {
            s1 += __shfl_xor_sync(0xFFFFFFFFu, s1, o);
            q1 += __shfl_xor_sync(0xFFFFFFFFu, q1, o);
            s2 += __shfl_xor_sync(0xFFFFFFFFu, s2, o);
            q2 += __shfl_xor_sync(0xFFFFFFFFu, q2, o);
        }
        float m1 = s1 * (1.f / 128.f);
        float r1 = rsqrtf(q1 * (1.f / 128.f) - m1 * m1 + 1e-5f);
        float m2 = s2 * (1.f / 128.f);
        float r2 = rsqrtf(q2 * (1.f / 128.f) - m2 * m2 + 1e-5f);

        if (l == 3) {
#pragma unroll
            for (int j = 0; j < 16; j++) {
                int col = j * 8 + 2 * t4;
                float2 gg = __ldg((const float2*)(gamma + col));
                float2 ee = __ldg((const float2*)(beta + col));
                if (grow1 < NN) {
                    float2 o1;
                    o1.x = fast_tanh((c[j][0] - m1) * r1 * gg.x + ee.x);
                    o1.y = fast_tanh((c[j][1] - m1) * r1 * gg.y + ee.y);
                    *(float2*)(out + (size_t)grow1 * DD + col) = o1;
                }
                if (grow2 < NN) {
                    float2 o2;
                    o2.x = fast_tanh((c[j][2] - m2) * r2 * gg.x + ee.x);
                    o2.y = fast_tanh((c[j][3] - m2) * r2 * gg.y + ee.y);
                    *(float2*)(out + (size_t)grow2 * DD + col) = o2;
                }
            }
            break;
        }

        // Intermediate: write tf32 h into H (warp-private rows)
#pragma unroll
        for (int j = 0; j < 16; j++) {
            int col = j * 8 + 2 * t4;
            float2 gg = __ldg((const float2*)(gamma + col));
            float2 ee = __ldg((const float2*)(beta + col));
            float h00 = fast_tanh((c[j][0] - m1) * r1 * gg.x + ee.x);
            float h01 = fast_tanh((c[j][1] - m1) * r1 * gg.y + ee.y);
            float h10 = fast_tanh((c[j][2] - m2) * r2 * gg.x + ee.x);
            float h11 = fast_tanh((c[j][3] - m2) * r2 * gg.y + ee.y);
            uint32_t* p1 = H + (wrow + g) * HSTRIDE + col;
            uint32_t* p2 = H + (wrow + g + 8) * HSTRIDE + col;
            p1[0] = f2tf32(h00); p1[1] = f2tf32(h01);
            p2[0] = f2tf32(h10); p2[1] = f2tf32(h11);
            c[j][0] = 0.f; c[j][1] = 0.f; c[j][2] = 0.f; c[j][3] = 0.f;
        }

        // Next layer GEMM: h (in H) @ W[l]  (K = 128)
        const float4* W4 = (const float4*)(W + (size_t)l * 128 * 128);
        for (int kc = 0; kc < 4; kc++) {
            __syncthreads();   // prior WB reads done; H writes are warp-private
#pragma unroll
            for (int i = 0; i < 4; i++) {
                int idx = tid + i * MLP_THREADS;
                int k = idx >> 5;
                int n4 = idx & 31;
                float4 v = __ldg(&W4[(size_t)(kc * 32 + k) * 32 + n4]);
                int ks = k >> 3, r = k & 7;
                int slot = r >> 2, t4w = r & 3;
                float vv[4] = {v.x, v.y, v.z, v.w};
#pragma unroll
                for (int cc = 0; cc < 4; cc++) {
                    int n = n4 * 4 + cc;
                    int jj = n >> 3, gg = n & 7;
                    WB[(ks * 32 + gg * 4 + t4w) * WBSTRIDE + jj * 2 + slot] = f2tf32(vv[cc]);
                }
            }
            __syncthreads();

#pragma unroll
            for (int ks = 0; ks < 4; ks++) {
                int kidx = kc * 32 + ks * 8 + t4;
                uint32_t a0 = H[(wrow + g) * HSTRIDE + kidx];
                uint32_t a1 = H[(wrow + g + 8) * HSTRIDE + kidx];
                uint32_t a2 = H[(wrow + g) * HSTRIDE + kidx + 4];
                uint32_t a3 = H[(wrow + g + 8) * HSTRIDE + kidx + 4];
                const uint4* wb = (const uint4*)(WB + (ks * 32 + lane) * WBSTRIDE);
#pragma unroll
                for (int q = 0; q < 8; q++) {
                    uint4 bb = wb[q];
                    MMA4(c[2 * q],     a0, a1, a2, a3, bb.x, bb.y);
                    MMA4(c[2 * q + 1], a0, a1, a2, a3, bb.z, bb.w);
                }
            }
        }
        __syncthreads();
    }
}

// ---------------------------------------------------------------------------
extern "C" void kernel_launch(void* const* d_in, const int* in_sizes, int n_in,
                              void* d_out, int out_size) {
    const float* x   = (const float*)d_in[0];
    const float* e   = (const float*)d_in[1];
    const int*   ei  = (const int*)d_in[2];
    const float* W0  = (const float*)d_in[3];
    const float* b0  = (const float*)d_in[4];
    const float* g0  = (const float*)d_in[5];
    const float* be0 = (const float*)d_in[6];
    const float* W   = (const float*)d_in[7];
    const float* b   = (const float*)d_in[8];
    const float* g   = (const float*)d_in[9];
    const float* be  = (const float*)d_in[10];
    float* out = (float*)d_out;

    float *mi, *mo;
    int *cnt, *offin, *offout, *curin, *curout;
    int2 *lin, *lout;
    cudaGetSymbolAddress((void**)&mi, g_mi);
    cudaGetSymbolAddress((void**)&mo, g_mo);
    cudaGetSymbolAddress((void**)&cnt, g_cnt);
    cudaGetSymbolAddress((void**)&offin, g_off_in);
    cudaGetSymbolAddress((void**)&offout, g_off_out);
    cudaGetSymbolAddress((void**)&curin, g_cur_in);
    cudaGetSymbolAddress((void**)&curout, g_cur_out);
    cudaGetSymbolAddress((void**)&lin, g_lst_in);
    cudaGetSymbolAddress((void**)&lout, g_lst_out);

    const int smem_bytes = (TILE_M * HSTRIDE + 4 * 32 * WBSTRIDE) * 4;  // ~86 KB
    cudaFuncSetAttribute(mlp_fused,
                         cudaFuncAttributeMaxDynamicSharedMemorySize,
                         smem_bytes);

    cudaMemsetAsync(cnt, 0, 2 * NN * sizeof(int));

    hist_kernel<<<(NE / 4 + 255) / 256, 256>>>(ei, cnt);
    scan_kernel<<<2, 1024>>>(cnt, offin, curin, offout, curout);
    fill_kernel<<<(NE / 4 + 255) / 256, 256>>>(ei, e, curin, curout, lin, lout);

    {
        long long warps = 2LL * NN;
        int blocks = (int)((warps * 32 + 255) / 256);
        gather_kernel<<<blocks, 256>>>(x, offin, lin, offout, lout, mi, mo);
    }

    const int gblocks = (NN + TILE_M - 1) / TILE_M;  // 782
    mlp_fused<<<gblocks, MLP_THREADS, smem_bytes>>>(
        mi, mo, x, W0, b0, g0, be0, W, b, g, be, out);
}

// round 6
// speedup vs baseline: 1.2977x; 1.1410x over previous
#include <cuda_runtime.h>
#include <math.h>
#include <stdint.h>

#define NN 100000
#define DD 128
#define NE 1600000

#define HSTRIDE 132
#define MLP_THREADS 128          // 4 warps; each warp owns 32 rows
#define ROWS_PER_BLOCK 128
#define N_CHUNKS 24              // 12 layer-0 (384 k) + 12 inner (3 layers x 128 k)

// Scratch (allocation-free rule: __device__ globals)
__device__ float g_mi[(size_t)NN * DD];
__device__ float g_mo[(size_t)NN * DD];

__device__ int   g_cnt[2 * NN];       // [0,NN): in-degree, [NN,2NN): out-degree
__device__ int   g_cursors[2];
__device__ int   g_off_in[NN];
__device__ int   g_off_out[NN];
__device__ int   g_cur_in[NN];
__device__ int   g_cur_out[NN];
__device__ int2  g_lst_in[NE];
__device__ int2  g_lst_out[NE];
__device__ uint4 g_wfrag[N_CHUNKS * 4 * 8 * 32];   // frag-major tf32 weights

// ---------------------------------------------------------------------------
__device__ __forceinline__ uint32_t f2tf32(float v) {
    uint32_t r;
    asm("cvt.rna.tf32.f32 %0, %1;" : "=r"(r) : "f"(v));
    return r;
}

__device__ __forceinline__ float fast_tanh(float x) {
    float ax = fabsf(x);
    float t = __expf(-2.f * ax);
    float r = (1.f - t) * __frcp_rn(1.f + t);
    return copysignf(r, x);
}

// ---------------------------------------------------------------------------
// Transform W0 [384,128] and W [3,128,128] into fragment-major tf32:
// uint4 index = ((chunk*4 + ks)*8 + q)*32 + lane, holding
// { B[k0][n0], B[k0+4][n0], B[k0][n1], B[k0+4][n1] } with
// k0 = 32*(chunk%4|...) + ks*8 + t4, n0 = q*16 + g, n1 = n0 + 8.
// ---------------------------------------------------------------------------
__global__ void wfrag_kernel(const float* __restrict__ W0,
                             const float* __restrict__ W,
                             uint4* __restrict__ WF) {
    int idx = blockIdx.x * blockDim.x + threadIdx.x;
    if (idx >= N_CHUNKS * 4 * 8 * 32) return;
    int lane = idx & 31;
    int q = (idx >> 5) & 7;
    int ks = (idx >> 8) & 3;
    int chunk = idx >> 10;
    int t4 = lane & 3, g = lane >> 2;
    int n0 = q * 16 + g;
    int n1 = n0 + 8;

    float w00, w01, w10, w11;
    if (chunk < 12) {
        int r = chunk * 32 + ks * 8 + t4;     // row in W0 (chunk*32 == m*128+kc*32)
        w00 = __ldg(&W0[(size_t)r * 128 + n0]);
        w01 = __ldg(&W0[(size_t)(r + 4) * 128 + n0]);
        w10 = __ldg(&W0[(size_t)r * 128 + n1]);
        w11 = __ldg(&W0[(size_t)(r + 4) * 128 + n1]);
    } else {
        int c2 = chunk - 12;
        int l = c2 >> 2;
        int r = (c2 & 3) * 32 + ks * 8 + t4;
        const float* Wl = W + (size_t)l * 128 * 128;
        w00 = __ldg(&Wl[(size_t)r * 128 + n0]);
        w01 = __ldg(&Wl[(size_t)(r + 4) * 128 + n0]);
        w10 = __ldg(&Wl[(size_t)r * 128 + n1]);
        w11 = __ldg(&Wl[(size_t)(r + 4) * 128 + n1]);
    }
    uint4 o;
    o.x = f2tf32(w00); o.y = f2tf32(w01);
    o.z = f2tf32(w10); o.w = f2tf32(w11);
    WF[idx] = o;
}

// ---------------------------------------------------------------------------
// Histogram of edge endpoints (4 edges per thread)
// ---------------------------------------------------------------------------
__global__ void hist_kernel(const int* __restrict__ ei, int* __restrict__ cnt) {
    int i = blockIdx.x * blockDim.x + threadIdx.x;
    if (i >= NE / 4) return;
    int4 s = __ldg((const int4*)ei + i);
    int4 t = __ldg((const int4*)(ei + NE) + i);
    atomicAdd(&cnt[t.x], 1); atomicAdd(&cnt[t.y], 1);
    atomicAdd(&cnt[t.z], 1); atomicAdd(&cnt[t.w], 1);
    atomicAdd(&cnt[NN + s.x], 1); atomicAdd(&cnt[NN + s.y], 1);
    atomicAdd(&cnt[NN + s.z], 1); atomicAdd(&cnt[NN + s.w], 1);
}

// ---------------------------------------------------------------------------
// Parallel segment allocation: CSR offsets need not be ordered.
// Warp-aggregated atomicAdd on a global cursor + shuffle prefix scan.
// (NN % 32 == 0, so no warp straddles the in/out halves.)
// ---------------------------------------------------------------------------
__global__ void alloc_kernel(const int* __restrict__ cnt,
                             int* __restrict__ offin, int* __restrict__ curin,
                             int* __restrict__ offout, int* __restrict__ curout,
                             int* __restrict__ cursors) {
    int i = blockIdx.x * blockDim.x + threadIdx.x;
    if (i >= 2 * NN) return;
    int lane = threadIdx.x & 31;
    int c = cnt[i];
    int inc = c;
#pragma unroll
    for (int o = 1; o < 32; o <<= 1) {
        int v = __shfl_up_sync(0xFFFFFFFFu, inc, o);
        if (lane >= o) inc += v;
    }
    int tot = __shfl_sync(0xFFFFFFFFu, inc, 31);
    int ex = inc - c;
    int half = (i < NN) ? 0 : 1;
    int base = 0;
    if (lane == 0) base = atomicAdd(&cursors[half], tot);
    base = __shfl_sync(0xFFFFFFFFu, base, 0);
    int off = base + ex;
    if (half == 0) { offin[i] = off; curin[i] = off; }
    else           { offout[i - NN] = off; curout[i - NN] = off; }
}

// ---------------------------------------------------------------------------
// Fill CSR edge lists (atomic cursors), 4 edges per thread
// ---------------------------------------------------------------------------
__global__ void fill_kernel(const int* __restrict__ ei, const float* __restrict__ e,
                            int* __restrict__ curin, int* __restrict__ curout,
                            int2* __restrict__ lin, int2* __restrict__ lout) {
    int i = blockIdx.x * blockDim.x + threadIdx.x;
    if (i >= NE / 4) return;
    int4 s = __ldg((const int4*)ei + i);
    int4 t = __ldg((const int4*)(ei + NE) + i);
    float4 w = __ldg((const float4*)e + i);
    int ss[4] = {s.x, s.y, s.z, s.w};
    int tt[4] = {t.x, t.y, t.z, t.w};
    float ww[4] = {w.x, w.y, w.z, w.w};
#pragma unroll
    for (int u = 0; u < 4; u++) {
        int wb = __float_as_int(ww[u]);
        int p1 = atomicAdd(&curin[tt[u]], 1);
        lin[p1] = make_int2(ss[u], wb);
        int p2 = atomicAdd(&curout[ss[u]], 1);
        lout[p2] = make_int2(tt[u], wb);
    }
}

// ---------------------------------------------------------------------------
// Merged gather: warps [0, NN) -> mi via lin; warps [NN, 2NN) -> mo via lout.
// Segment length from cnt (offsets are unordered).
// ---------------------------------------------------------------------------
__global__ __launch_bounds__(256) void gather_kernel(
    const float* __restrict__ x, const int* __restrict__ cnt,
    const int* __restrict__ offin, const int2* __restrict__ lin,
    const int* __restrict__ offout, const int2* __restrict__ lout,
    float* __restrict__ mi, float* __restrict__ mo) {
    int wg = (blockIdx.x * blockDim.x + threadIdx.x) >> 5;
    int lane = threadIdx.x & 31;
    if (wg >= 2 * NN) return;

    const int* off;
    const int2* lst;
    float* dst;
    int node;
    if (wg < NN) { node = wg; off = offin; lst = lin; dst = mi; }
    else         { node = wg - NN; off = offout; lst = lout; dst = mo; }

    int beg = off[node];
    int end = beg + cnt[wg];

    float4 acc = make_float4(0.f, 0.f, 0.f, 0.f);

    int j = beg;
    for (; j + 8 <= end; j += 8) {
        int2 p[8];
#pragma unroll
        for (int u = 0; u < 8; u++) p[u] = __ldg(&lst[j + u]);
        float4 v[8];
#pragma unroll
        for (int u = 0; u < 8; u++)
            v[u] = __ldg((const float4*)(x + (size_t)p[u].x * DD) + lane);
#pragma unroll
        for (int u = 0; u < 8; u++) {
            float w = __int_as_float(p[u].y);
            acc.x = fmaf(w, v[u].x, acc.x); acc.y = fmaf(w, v[u].y, acc.y);
            acc.z = fmaf(w, v[u].z, acc.z); acc.w = fmaf(w, v[u].w, acc.w);
        }
    }
    for (; j < end; j++) {
        int2 p0 = __ldg(&lst[j]);
        float4 v0 = __ldg((const float4*)(x + (size_t)p0.x * DD) + lane);
        float w0 = __int_as_float(p0.y);
        acc.x = fmaf(w0, v0.x, acc.x); acc.y = fmaf(w0, v0.y, acc.y);
        acc.z = fmaf(w0, v0.z, acc.z); acc.w = fmaf(w0, v0.w, acc.w);
    }

    ((float4*)(dst + (size_t)node * DD))[lane] = acc;
}

// ---------------------------------------------------------------------------
// Fused 4-layer MLP, sync-free: warp owns 32 rows (two m16 tiles).
// B-fragments read directly from the frag-major global buffer (L1-cached,
// shared across warps). h kept in a per-warp smem slab; only __syncwarp().
// ---------------------------------------------------------------------------
#define MMA4(cj, A0r, A1r, A2r, A3r, B0r, B1r)                                   \
    asm volatile(                                                                \
        "mma.sync.aligned.m16n8k8.row.col.f32.tf32.tf32.f32 "                    \
        "{%0,%1,%2,%3}, {%4,%5,%6,%7}, {%8,%9}, {%0,%1,%2,%3};"                  \
        : "+f"(cj[0]), "+f"(cj[1]), "+f"(cj[2]), "+f"(cj[3])                     \
        : "r"(A0r), "r"(A1r), "r"(A2r), "r"(A3r), "r"(B0r), "r"(B1r))

__global__ __launch_bounds__(MLP_THREADS, 2) void mlp_fused(
    const float* __restrict__ A0, const float* __restrict__ A1,
    const float* __restrict__ A2,
    const uint4* __restrict__ WF,
    const float* __restrict__ b0v, const float* __restrict__ g0v,
    const float* __restrict__ be0v,
    const float* __restrict__ bv, const float* __restrict__ gv,
    const float* __restrict__ bev,
    float* __restrict__ out)
{
    extern __shared__ uint32_t smem[];
    const int tid = threadIdx.x;
    const int lane = tid & 31;
    const int wid = tid >> 5;
    const int g = lane >> 2;
    const int t4 = lane & 3;
    const int row0 = blockIdx.x * ROWS_PER_BLOCK + wid * 32;

    uint32_t* Hw = smem + wid * 32 * HSTRIDE;   // per-warp slab [32][HSTRIDE]

    float c[2][16][4];
#pragma unroll
    for (int t = 0; t < 2; t++)
#pragma unroll
        for (int j = 0; j < 16; j++)
#pragma unroll
            for (int q = 0; q < 4; q++) c[t][j][q] = 0.f;

    // Row indices for the two m16 tiles (clamped reads, guarded writes)
    int r00 = row0 + g;        // tile0 rows: r00, r00+8
    int r10 = row0 + 16 + g;   // tile1 rows: r10, r10+8
    int cr00 = r00 < NN ? r00 : 0;
    int cr01 = (r00 + 8) < NN ? (r00 + 8) : 0;
    int cr10 = r10 < NN ? r10 : 0;
    int cr11 = (r10 + 8) < NN ? (r10 + 8) : 0;

    // ---------------- Layer 0: K = 384 over {mi, mo, x} ----------------
    const float* Ap[3] = {A0, A1, A2};
#pragma unroll 1
    for (int m = 0; m < 3; m++) {
        const float* A = Ap[m];
#pragma unroll
        for (int kc = 0; kc < 4; kc++) {
            int chunk = m * 4 + kc;
#pragma unroll
            for (int ks = 0; ks < 4; ks++) {
                int kidx = kc * 32 + ks * 8 + t4;
                uint32_t a0[4], a1[4];
                a0[0] = f2tf32(__ldg(A + (size_t)cr00 * DD + kidx));
                a0[1] = f2tf32(__ldg(A + (size_t)cr01 * DD + kidx));
                a0[2] = f2tf32(__ldg(A + (size_t)cr00 * DD + kidx + 4));
                a0[3] = f2tf32(__ldg(A + (size_t)cr01 * DD + kidx + 4));
                a1[0] = f2tf32(__ldg(A + (size_t)cr10 * DD + kidx));
                a1[1] = f2tf32(__ldg(A + (size_t)cr11 * DD + kidx));
                a1[2] = f2tf32(__ldg(A + (size_t)cr10 * DD + kidx + 4));
                a1[3] = f2tf32(__ldg(A + (size_t)cr11 * DD + kidx + 4));
                const uint4* wfk = WF + ((size_t)(chunk * 4 + ks) << 8);
#pragma unroll
                for (int q = 0; q < 8; q++) {
                    uint4 bb = __ldg(&wfk[(q << 5) + lane]);
                    MMA4(c[0][2 * q],     a0[0], a0[1], a0[2], a0[3], bb.x, bb.y);
                    MMA4(c[0][2 * q + 1], a0[0], a0[1], a0[2], a0[3], bb.z, bb.w);
                    MMA4(c[1][2 * q],     a1[0], a1[1], a1[2], a1[3], bb.x, bb.y);
                    MMA4(c[1][2 * q + 1], a1[0], a1[1], a1[2], a1[3], bb.z, bb.w);
                }
            }
        }
    }

    // ---------------- 4 epilogues + 3 inner layers (sync-free) ----------------
#pragma unroll 1
    for (int l = 0; l < 4; l++) {
        const float* bias  = (l == 0) ? b0v  : bv  + (l - 1) * 128;
        const float* gamma = (l == 0) ? g0v  : gv  + (l - 1) * 128;
        const float* beta  = (l == 0) ? be0v : bev + (l - 1) * 128;

        float s[2][2], qq[2][2];
#pragma unroll
        for (int t = 0; t < 2; t++) { s[t][0]=s[t][1]=qq[t][0]=qq[t][1]=0.f; }

#pragma unroll
        for (int j = 0; j < 16; j++) {
            int col = j * 8 + 2 * t4;
            float2 bb = __ldg((const float2*)(bias + col));
#pragma unroll
            for (int t = 0; t < 2; t++) {
                c[t][j][0] += bb.x; c[t][j][1] += bb.y;
                c[t][j][2] += bb.x; c[t][j][3] += bb.y;
                s[t][0]  += c[t][j][0] + c[t][j][1];
                qq[t][0] += c[t][j][0] * c[t][j][0] + c[t][j][1] * c[t][j][1];
                s[t][1]  += c[t][j][2] + c[t][j][3];
                qq[t][1] += c[t][j][2] * c[t][j][2] + c[t][j][3] * c[t][j][3];
            }
        }
#pragma unroll
        for (int o = 1; o <= 2; o <<= 1) {
#pragma unroll
            for (int t = 0; t < 2; t++) {
                s[t][0]  += __shfl_xor_sync(0xFFFFFFFFu, s[t][0], o);
                qq[t][0] += __shfl_xor_sync(0xFFFFFFFFu, qq[t][0], o);
                s[t][1]  += __shfl_xor_sync(0xFFFFFFFFu, s[t][1], o);
                qq[t][1] += __shfl_xor_sync(0xFFFFFFFFu, qq[t][1], o);
            }
        }
        float mean[2][2], rstd[2][2];
#pragma unroll
        for (int t = 0; t < 2; t++)
#pragma unroll
            for (int h = 0; h < 2; h++) {
                mean[t][h] = s[t][h] * (1.f / 128.f);
                rstd[t][h] = rsqrtf(qq[t][h] * (1.f / 128.f) - mean[t][h] * mean[t][h] + 1e-5f);
            }

        if (l == 3) {
#pragma unroll
            for (int j = 0; j < 16; j++) {
                int col = j * 8 + 2 * t4;
                float2 gg = __ldg((const float2*)(gamma + col));
                float2 ee = __ldg((const float2*)(beta + col));
#pragma unroll
                for (int t = 0; t < 2; t++) {
                    int ra = row0 + t * 16 + g;
                    int rb = ra + 8;
                    if (ra < NN) {
                        float2 o1;
                        o1.x = fast_tanh((c[t][j][0] - mean[t][0]) * rstd[t][0] * gg.x + ee.x);
                        o1.y = fast_tanh((c[t][j][1] - mean[t][0]) * rstd[t][0] * gg.y + ee.y);
                        *(float2*)(out + (size_t)ra * DD + col) = o1;
                    }
                    if (rb < NN) {
                        float2 o2;
                        o2.x = fast_tanh((c[t][j][2] - mean[t][1]) * rstd[t][1] * gg.x + ee.x);
                        o2.y = fast_tanh((c[t][j][3] - mean[t][1]) * rstd[t][1] * gg.y + ee.y);
                        *(float2*)(out + (size_t)rb * DD + col) = o2;
                    }
                }
            }
            break;
        }

        // Write h (tf32) into per-warp smem slab
#pragma unroll
        for (int j = 0; j < 16; j++) {
            int col = j * 8 + 2 * t4;
            float2 gg = __ldg((const float2*)(gamma + col));
            float2 ee = __ldg((const float2*)(beta + col));
#pragma unroll
            for (int t = 0; t < 2; t++) {
                float h00 = fast_tanh((c[t][j][0] - mean[t][0]) * rstd[t][0] * gg.x + ee.x);
                float h01 = fast_tanh((c[t][j][1] - mean[t][0]) * rstd[t][0] * gg.y + ee.y);
                float h10 = fast_tanh((c[t][j][2] - mean[t][1]) * rstd[t][1] * gg.x + ee.x);
                float h11 = fast_tanh((c[t][j][3] - mean[t][1]) * rstd[t][1] * gg.y + ee.y);
                uint32_t* p1 = Hw + (t * 16 + g) * HSTRIDE + col;
                uint32_t* p2 = Hw + (t * 16 + g + 8) * HSTRIDE + col;
                p1[0] = f2tf32(h00); p1[1] = f2tf32(h01);
                p2[0] = f2tf32(h10); p2[1] = f2tf32(h11);
                c[t][j][0] = 0.f; c[t][j][1] = 0.f;
                c[t][j][2] = 0.f; c[t][j][3] = 0.f;
            }
        }
        __syncwarp();

        // Next layer GEMM: h (in Hw) @ W[l], K = 128
#pragma unroll
        for (int kc = 0; kc < 4; kc++) {
            int chunk = 12 + l * 4 + kc;
#pragma unroll
            for (int ks = 0; ks < 4; ks++) {
                int kidx = kc * 32 + ks * 8 + t4;
                uint32_t a0[4], a1[4];
                a0[0] = Hw[(g) * HSTRIDE + kidx];
                a0[1] = Hw[(g + 8) * HSTRIDE + kidx];
                a0[2] = Hw[(g) * HSTRIDE + kidx + 4];
                a0[3] = Hw[(g + 8) * HSTRIDE + kidx + 4];
                a1[0] = Hw[(16 + g) * HSTRIDE + kidx];
                a1[1] = Hw[(24 + g) * HSTRIDE + kidx];
                a1[2] = Hw[(16 + g) * HSTRIDE + kidx + 4];
                a1[3] = Hw[(24 + g) * HSTRIDE + kidx + 4];
                const uint4* wfk = WF + ((size_t)(chunk * 4 + ks) << 8);
#pragma unroll
                for (int q = 0; q < 8; q++) {
                    uint4 bb = __ldg(&wfk[(q << 5) + lane]);
                    MMA4(c[0][2 * q],     a0[0], a0[1], a0[2], a0[3], bb.x, bb.y);
                    MMA4(c[0][2 * q + 1], a0[0], a0[1], a0[2], a0[3], bb.z, bb.w);
                    MMA4(c[1][2 * q],     a1[0], a1[1], a1[2], a1[3], bb.x, bb.y);
                    MMA4(c[1][2 * q + 1], a1[0], a1[1], a1[2], a1[3], bb.z, bb.w);
                }
            }
        }
        __syncwarp();
    }
}

// ---------------------------------------------------------------------------
extern "C" void kernel_launch(void* const* d_in, const int* in_sizes, int n_in,
                              void* d_out, int out_size) {
    const float* x   = (const float*)d_in[0];
    const float* e   = (const float*)d_in[1];
    const int*   ei  = (const int*)d_in[2];
    const float* W0  = (const float*)d_in[3];
    const float* b0  = (const float*)d_in[4];
    const float* g0  = (const float*)d_in[5];
    const float* be0 = (const float*)d_in[6];
    const float* W   = (const float*)d_in[7];
    const float* b   = (const float*)d_in[8];
    const float* g   = (const float*)d_in[9];
    const float* be  = (const float*)d_in[10];
    float* out = (float*)d_out;

    float *mi, *mo;
    int *cnt, *cursors, *offin, *offout, *curin, *curout;
    int2 *lin, *lout;
    uint4* wf;
    cudaGetSymbolAddress((void**)&mi, g_mi);
    cudaGetSymbolAddress((void**)&mo, g_mo);
    cudaGetSymbolAddress((void**)&cnt, g_cnt);
    cudaGetSymbolAddress((void**)&cursors, g_cursors);
    cudaGetSymbolAddress((void**)&offin, g_off_in);
    cudaGetSymbolAddress((void**)&offout, g_off_out);
    cudaGetSymbolAddress((void**)&curin, g_cur_in);
    cudaGetSymbolAddress((void**)&curout, g_cur_out);
    cudaGetSymbolAddress((void**)&lin, g_lst_in);
    cudaGetSymbolAddress((void**)&lout, g_lst_out);
    cudaGetSymbolAddress((void**)&wf, g_wfrag);

    const int smem_bytes = 4 * 32 * HSTRIDE * 4;   // 4 warps x 32 rows x 132 words
    cudaFuncSetAttribute(mlp_fused,
                         cudaFuncAttributeMaxDynamicSharedMemorySize,
                         smem_bytes);

    cudaMemsetAsync(cnt, 0, 2 * NN * sizeof(int));
    cudaMemsetAsync(cursors, 0, 2 * sizeof(int));

    wfrag_kernel<<<(N_CHUNKS * 1024 + 255) / 256, 256>>>(W0, W, wf);
    hist_kernel<<<(NE / 4 + 255) / 256, 256>>>(ei, cnt);
    alloc_kernel<<<(2 * NN + 255) / 256, 256>>>(cnt, offin, curin, offout, curout, cursors);
    fill_kernel<<<(NE / 4 + 255) / 256, 256>>>(ei, e, curin, curout, lin, lout);

    {
        long long warps = 2LL * NN;
        int blocks = (int)((warps * 32 + 255) / 256);
        gather_kernel<<<blocks, 256>>>(x, cnt, offin, lin, offout, lout, mi, mo);
    }

    const int gblocks = (NN + ROWS_PER_BLOCK - 1) / ROWS_PER_BLOCK;  // 782
    mlp_fused<<<gblocks, MLP_THREADS, smem_bytes>>>(
        mi, mo, x, wf, b0, g0, be0, b, g, be, out);
}